// round 1
// baseline (speedup 1.0000x reference)
#include <cuda_runtime.h>

#define SEQ 400
#define BATCH 8
#define DM 256          // d_model
#define SD 512          // source_dim
#define NDELTA 800      // 799 distinct deltas, padded to 800
#define BS (BATCH*SEQ)          // 3200
#define BSS (BATCH*SEQ*SEQ)     // 1280000

// Scratch (device globals — no allocations allowed)
__device__ float g_W2[SD*DM];        // w_q2 @ w_k2^T          (512x256)
__device__ float g_RT[DM*NDELTA];    // R^T: [d][delta+399]    (256x800)
__device__ float g_Q[BS*DM];         // x @ w_q                (3200x256)
__device__ float g_K[BS*DM];         // x @ w_k
__device__ float g_Q2W[BS*DM];       // x @ W2
__device__ float g_E[BATCH*SEQ*SEQ]; // batched Q K^T          (8x400x400)
__device__ float g_S[BS*NDELTA];     // Q2W @ RT               (3200x800)

// ---------------------------------------------------------------------------
// Generic 64x64 tile SGEMM, 256 threads, 4x4 micro-tile, BK=16.
// NT=false: C[M,N] = A[M,K] @ B[K,N]   (both row-major)
// NT=true : C[M,N] = A[M,K] @ B[N,K]^T (B row-major, N x K)
// Requires K % 16 == 0 (true for 256/512). M, N arbitrary (bounds-checked).
// blockIdx.z batching via element strides.
// ---------------------------------------------------------------------------
template <bool NT>
__global__ __launch_bounds__(256)
void sgemm64(const float* __restrict__ A, const float* __restrict__ B,
             float* __restrict__ C, int M, int N, int K,
             long strideA, long strideB, long strideC)
{
    __shared__ float As[16][68];
    __shared__ float Bs[16][68];

    A += blockIdx.z * strideA;
    B += blockIdx.z * strideB;
    C += blockIdx.z * strideC;

    const int m0 = blockIdx.y * 64;
    const int n0 = blockIdx.x * 64;
    const int tid = threadIdx.x;
    const int tx = tid & 15;
    const int ty = tid >> 4;

    float acc[4][4];
#pragma unroll
    for (int r = 0; r < 4; r++)
#pragma unroll
        for (int c = 0; c < 4; c++) acc[r][c] = 0.f;

    for (int k0 = 0; k0 < K; k0 += 16) {
        // ---- load A tile: As[kk][row] = A[m0+row][k0+kk]
        {
            const int ar = tid >> 2;          // 0..63
            const int ak = (tid & 3) * 4;     // 0,4,8,12
            const int gm = m0 + ar;
            float4 v = make_float4(0.f, 0.f, 0.f, 0.f);
            if (gm < M) v = *(const float4*)(A + (long)gm * K + k0 + ak);
            As[ak + 0][ar] = v.x;
            As[ak + 1][ar] = v.y;
            As[ak + 2][ar] = v.z;
            As[ak + 3][ar] = v.w;
        }
        // ---- load B tile: Bs[kk][col]
        if (NT) {
            // B is N x K: Bs[kk][col] = B[n0+col][k0+kk]
            const int br = tid >> 2;
            const int bk = (tid & 3) * 4;
            const int gn = n0 + br;
            float4 v = make_float4(0.f, 0.f, 0.f, 0.f);
            if (gn < N) v = *(const float4*)(B + (long)gn * K + k0 + bk);
            Bs[bk + 0][br] = v.x;
            Bs[bk + 1][br] = v.y;
            Bs[bk + 2][br] = v.z;
            Bs[bk + 3][br] = v.w;
        } else {
            // B is K x N: Bs[kk][col] = B[k0+kk][n0+col]
            const int bk = tid >> 4;          // 0..15
            const int bc = (tid & 15) * 4;    // 0..60
            const int gn = n0 + bc;
            float4 v = make_float4(0.f, 0.f, 0.f, 0.f);
            const float* brow = B + (long)(k0 + bk) * N;
            if (gn + 3 < N) {
                v = *(const float4*)(brow + gn);
            } else {
                if (gn + 0 < N) v.x = brow[gn + 0];
                if (gn + 1 < N) v.y = brow[gn + 1];
                if (gn + 2 < N) v.z = brow[gn + 2];
                if (gn + 3 < N) v.w = brow[gn + 3];
            }
            *(float4*)&Bs[bk][bc] = v;
        }
        __syncthreads();

#pragma unroll
        for (int kk = 0; kk < 16; kk++) {
            const float4 a = *(const float4*)&As[kk][ty * 4];
            const float4 b = *(const float4*)&Bs[kk][tx * 4];
            acc[0][0] += a.x * b.x; acc[0][1] += a.x * b.y; acc[0][2] += a.x * b.z; acc[0][3] += a.x * b.w;
            acc[1][0] += a.y * b.x; acc[1][1] += a.y * b.y; acc[1][2] += a.y * b.z; acc[1][3] += a.y * b.w;
            acc[2][0] += a.z * b.x; acc[2][1] += a.z * b.y; acc[2][2] += a.z * b.z; acc[2][3] += a.z * b.w;
            acc[3][0] += a.w * b.x; acc[3][1] += a.w * b.y; acc[3][2] += a.w * b.z; acc[3][3] += a.w * b.w;
        }
        __syncthreads();
    }

#pragma unroll
    for (int r = 0; r < 4; r++) {
        const int gm = m0 + ty * 4 + r;
        if (gm >= M) continue;
#pragma unroll
        for (int c = 0; c < 4; c++) {
            const int gn = n0 + tx * 4 + c;
            if (gn < N) C[(long)gm * N + gn] = acc[r][c];
        }
    }
}

// ---------------------------------------------------------------------------
// Build transposed relative table: RT[d][m] = rel_sinusoid[0, i, j, d]
// for any (i,j) with j-i == m-399. rel depends only on delta:
//   delta >= 0 -> (i=0, j=delta)   offset = delta*DM
//   delta <  0 -> (i=-delta, j=0)  offset = (-delta)*SEQ*DM
// m == 799 is padding (zero).
// ---------------------------------------------------------------------------
__global__ void build_rt(const float* __restrict__ rel, float* __restrict__ RT)
{
    const int m = blockIdx.x;     // 0..799
    const int d = threadIdx.x;    // 0..255
    float v = 0.f;
    if (m <= 798) {
        const int delta = m - 399;
        const long off = (delta >= 0) ? (long)delta * DM : (long)(-delta) * SEQ * DM;
        v = rel[off + d];
    }
    RT[(long)d * NDELTA + m] = v;
}

// ---------------------------------------------------------------------------
// out[b,i,j] = (E[b,i,j] + S[b,i, j-i+399]) / sqrt(256)
// second half of out (if present) = mask[b,i] * mask[b,j] as float
// ---------------------------------------------------------------------------
__global__ void combine(const float* __restrict__ E, const float* __restrict__ S,
                        const int* __restrict__ mask, float* __restrict__ out,
                        int out_size)
{
    const int idx = blockIdx.x * blockDim.x + threadIdx.x;
    if (idx >= BSS) return;
    const int j = idx % SEQ;
    const int bi = idx / SEQ;     // b*SEQ + i
    const int i = bi % SEQ;
    const int b = bi / SEQ;

    const float v = (E[idx] + S[(long)bi * NDELTA + (j - i + 399)]) * 0.0625f;
    out[idx] = v;
    if (out_size >= 2 * BSS) {
        out[BSS + idx] = (float)(mask[b * SEQ + i] * mask[b * SEQ + j]);
    }
}

extern "C" void kernel_launch(void* const* d_in, const int* in_sizes, int n_in,
                              void* d_out, int out_size)
{
    const float* x    = (const float*)d_in[0];  // (8,400,512)
    const int*   mask = (const int*)  d_in[1];  // (8,400)
    const float* w_q  = (const float*)d_in[2];  // (512,256)
    const float* w_q2 = (const float*)d_in[3];  // (512,256)
    const float* w_k  = (const float*)d_in[4];  // (512,256)
    const float* w_k2 = (const float*)d_in[5];  // (256,256)
    const float* rel  = (const float*)d_in[6];  // (1,400,400,256)
    float* out = (float*)d_out;

    float *W2, *RT, *Q, *Kb, *Q2W, *E, *S;
    cudaGetSymbolAddress((void**)&W2,  g_W2);
    cudaGetSymbolAddress((void**)&RT,  g_RT);
    cudaGetSymbolAddress((void**)&Q,   g_Q);
    cudaGetSymbolAddress((void**)&Kb,  g_K);
    cudaGetSymbolAddress((void**)&Q2W, g_Q2W);
    cudaGetSymbolAddress((void**)&E,   g_E);
    cudaGetSymbolAddress((void**)&S,   g_S);

    // W2 = w_q2 (512x256) @ w_k2^T (256x256)  -> (512x256)
    sgemm64<true><<<dim3((DM + 63) / 64, (SD + 63) / 64, 1), 256>>>(
        w_q2, w_k2, W2, SD, DM, DM, 0, 0, 0);

    // RT gather
    build_rt<<<NDELTA, DM>>>(rel, RT);

    // Q = x @ w_q ; K = x @ w_k ; Q2W = x @ W2   (3200x512 @ 512x256)
    dim3 gproj((DM + 63) / 64, (BS + 63) / 64, 1);
    sgemm64<false><<<gproj, 256>>>(x, w_q, Q,  BS, DM, SD, 0, 0, 0);
    sgemm64<false><<<gproj, 256>>>(x, w_k, Kb, BS, DM, SD, 0, 0, 0);
    sgemm64<false><<<gproj, 256>>>(x, W2,  Q2W, BS, DM, SD, 0, 0, 0);

    // S = Q2W (3200x256) @ RT (256x800)
    sgemm64<false><<<dim3((NDELTA + 63) / 64, (BS + 63) / 64, 1), 256>>>(
        Q2W, RT, S, BS, NDELTA, DM, 0, 0, 0);

    // E[b] = Q[b] (400x256) @ K[b]^T (400x256)^T, batched over z
    sgemm64<true><<<dim3((SEQ + 63) / 64, (SEQ + 63) / 64, BATCH), 256>>>(
        Q, Kb, E, SEQ, SEQ, DM,
        (long)SEQ * DM, (long)SEQ * DM, (long)SEQ * SEQ);

    // Final combine + mask
    combine<<<(BSS + 255) / 256, 256>>>(E, S, mask, out, out_size);
}

// round 2
// speedup vs baseline: 1.0001x; 1.0001x over previous
#include <cuda_runtime.h>

#define SEQ 400
#define BATCH 8
#define DM 256          // d_model
#define SD 512          // source_dim
#define NDELTA 800      // 799 distinct deltas, padded to 800
#define BS (BATCH*SEQ)          // 3200
#define BSS (BATCH*SEQ*SEQ)     // 1280000

// Scratch (device globals — no allocations allowed)
__device__ float g_W2[SD*DM];        // w_q2 @ w_k2^T          (512x256)
__device__ float g_RT[DM*NDELTA];    // R^T: [d][delta+399]    (256x800)
__device__ float g_Q[BS*DM];         // x @ w_q                (3200x256)
__device__ float g_K[BS*DM];         // x @ w_k
__device__ float g_Q2W[BS*DM];       // x @ W2
__device__ float g_E[BATCH*SEQ*SEQ]; // batched Q K^T          (8x400x400)
__device__ float g_S[BS*NDELTA];     // Q2W @ RT               (3200x800)

// ---------------------------------------------------------------------------
// Generic 64x64 tile SGEMM, 256 threads, 4x4 micro-tile, BK=16.
// NT=false: C[M,N] = A[M,K] @ B[K,N]   (both row-major)
// NT=true : C[M,N] = A[M,K] @ B[N,K]^T (B row-major, N x K)
// Requires K % 16 == 0 (true for 256/512). M, N arbitrary (bounds-checked).
// blockIdx.z batching via element strides.
// ---------------------------------------------------------------------------
template <bool NT>
__global__ __launch_bounds__(256)
void sgemm64(const float* __restrict__ A, const float* __restrict__ B,
             float* __restrict__ C, int M, int N, int K,
             long strideA, long strideB, long strideC)
{
    __shared__ float As[16][68];
    __shared__ float Bs[16][68];

    A += blockIdx.z * strideA;
    B += blockIdx.z * strideB;
    C += blockIdx.z * strideC;

    const int m0 = blockIdx.y * 64;
    const int n0 = blockIdx.x * 64;
    const int tid = threadIdx.x;
    const int tx = tid & 15;
    const int ty = tid >> 4;

    float acc[4][4];
#pragma unroll
    for (int r = 0; r < 4; r++)
#pragma unroll
        for (int c = 0; c < 4; c++) acc[r][c] = 0.f;

    for (int k0 = 0; k0 < K; k0 += 16) {
        // ---- load A tile: As[kk][row] = A[m0+row][k0+kk]
        {
            const int ar = tid >> 2;          // 0..63
            const int ak = (tid & 3) * 4;     // 0,4,8,12
            const int gm = m0 + ar;
            float4 v = make_float4(0.f, 0.f, 0.f, 0.f);
            if (gm < M) v = *(const float4*)(A + (long)gm * K + k0 + ak);
            As[ak + 0][ar] = v.x;
            As[ak + 1][ar] = v.y;
            As[ak + 2][ar] = v.z;
            As[ak + 3][ar] = v.w;
        }
        // ---- load B tile: Bs[kk][col]
        if (NT) {
            // B is N x K: Bs[kk][col] = B[n0+col][k0+kk]
            const int br = tid >> 2;
            const int bk = (tid & 3) * 4;
            const int gn = n0 + br;
            float4 v = make_float4(0.f, 0.f, 0.f, 0.f);
            if (gn < N) v = *(const float4*)(B + (long)gn * K + k0 + bk);
            Bs[bk + 0][br] = v.x;
            Bs[bk + 1][br] = v.y;
            Bs[bk + 2][br] = v.z;
            Bs[bk + 3][br] = v.w;
        } else {
            // B is K x N: Bs[kk][col] = B[k0+kk][n0+col]
            const int bk = tid >> 4;          // 0..15
            const int bc = (tid & 15) * 4;    // 0..60
            const int gn = n0 + bc;
            float4 v = make_float4(0.f, 0.f, 0.f, 0.f);
            const float* brow = B + (long)(k0 + bk) * N;
            if (gn + 3 < N) {
                v = *(const float4*)(brow + gn);
            } else {
                if (gn + 0 < N) v.x = brow[gn + 0];
                if (gn + 1 < N) v.y = brow[gn + 1];
                if (gn + 2 < N) v.z = brow[gn + 2];
                if (gn + 3 < N) v.w = brow[gn + 3];
            }
            *(float4*)&Bs[bk][bc] = v;
        }
        __syncthreads();

#pragma unroll
        for (int kk = 0; kk < 16; kk++) {
            const float4 a = *(const float4*)&As[kk][ty * 4];
            const float4 b = *(const float4*)&Bs[kk][tx * 4];
            acc[0][0] += a.x * b.x; acc[0][1] += a.x * b.y; acc[0][2] += a.x * b.z; acc[0][3] += a.x * b.w;
            acc[1][0] += a.y * b.x; acc[1][1] += a.y * b.y; acc[1][2] += a.y * b.z; acc[1][3] += a.y * b.w;
            acc[2][0] += a.z * b.x; acc[2][1] += a.z * b.y; acc[2][2] += a.z * b.z; acc[2][3] += a.z * b.w;
            acc[3][0] += a.w * b.x; acc[3][1] += a.w * b.y; acc[3][2] += a.w * b.z; acc[3][3] += a.w * b.w;
        }
        __syncthreads();
    }

#pragma unroll
    for (int r = 0; r < 4; r++) {
        const int gm = m0 + ty * 4 + r;
        if (gm >= M) continue;
#pragma unroll
        for (int c = 0; c < 4; c++) {
            const int gn = n0 + tx * 4 + c;
            if (gn < N) C[(long)gm * N + gn] = acc[r][c];
        }
    }
}

// ---------------------------------------------------------------------------
// Build transposed relative table: RT[d][m] = rel_sinusoid[0, i, j, d]
// for any (i,j) with j-i == m-399. rel depends only on delta:
//   delta >= 0 -> (i=0, j=delta)   offset = delta*DM
//   delta <  0 -> (i=-delta, j=0)  offset = (-delta)*SEQ*DM
// m == 799 is padding (zero).
// ---------------------------------------------------------------------------
__global__ void build_rt(const float* __restrict__ rel, float* __restrict__ RT)
{
    const int m = blockIdx.x;     // 0..799
    const int d = threadIdx.x;    // 0..255
    float v = 0.f;
    if (m <= 798) {
        const int delta = m - 399;
        const long off = (delta >= 0) ? (long)delta * DM : (long)(-delta) * SEQ * DM;
        v = rel[off + d];
    }
    RT[(long)d * NDELTA + m] = v;
}

// ---------------------------------------------------------------------------
// out[b,i,j] = (E[b,i,j] + S[b,i, j-i+399]) / sqrt(256)
// second half of out (if present) = mask[b,i] * mask[b,j] as float
// ---------------------------------------------------------------------------
__global__ void combine(const float* __restrict__ E, const float* __restrict__ S,
                        const int* __restrict__ mask, float* __restrict__ out,
                        int out_size)
{
    const int idx = blockIdx.x * blockDim.x + threadIdx.x;
    if (idx >= BSS) return;
    const int j = idx % SEQ;
    const int bi = idx / SEQ;     // b*SEQ + i
    const int i = bi % SEQ;
    const int b = bi / SEQ;

    const float v = (E[idx] + S[(long)bi * NDELTA + (j - i + 399)]) * 0.0625f;
    out[idx] = v;
    if (out_size >= 2 * BSS) {
        out[BSS + idx] = (float)(mask[b * SEQ + i] * mask[b * SEQ + j]);
    }
}

extern "C" void kernel_launch(void* const* d_in, const int* in_sizes, int n_in,
                              void* d_out, int out_size)
{
    const float* x    = (const float*)d_in[0];  // (8,400,512)
    const int*   mask = (const int*)  d_in[1];  // (8,400)
    const float* w_q  = (const float*)d_in[2];  // (512,256)
    const float* w_q2 = (const float*)d_in[3];  // (512,256)
    const float* w_k  = (const float*)d_in[4];  // (512,256)
    const float* w_k2 = (const float*)d_in[5];  // (256,256)
    const float* rel  = (const float*)d_in[6];  // (1,400,400,256)
    float* out = (float*)d_out;

    float *W2, *RT, *Q, *Kb, *Q2W, *E, *S;
    cudaGetSymbolAddress((void**)&W2,  g_W2);
    cudaGetSymbolAddress((void**)&RT,  g_RT);
    cudaGetSymbolAddress((void**)&Q,   g_Q);
    cudaGetSymbolAddress((void**)&Kb,  g_K);
    cudaGetSymbolAddress((void**)&Q2W, g_Q2W);
    cudaGetSymbolAddress((void**)&E,   g_E);
    cudaGetSymbolAddress((void**)&S,   g_S);

    // W2 = w_q2 (512x256) @ w_k2^T (256x256)  -> (512x256)
    sgemm64<true><<<dim3((DM + 63) / 64, (SD + 63) / 64, 1), 256>>>(
        w_q2, w_k2, W2, SD, DM, DM, 0, 0, 0);

    // RT gather
    build_rt<<<NDELTA, DM>>>(rel, RT);

    // Q = x @ w_q ; K = x @ w_k ; Q2W = x @ W2   (3200x512 @ 512x256)
    dim3 gproj((DM + 63) / 64, (BS + 63) / 64, 1);
    sgemm64<false><<<gproj, 256>>>(x, w_q, Q,  BS, DM, SD, 0, 0, 0);
    sgemm64<false><<<gproj, 256>>>(x, w_k, Kb, BS, DM, SD, 0, 0, 0);
    sgemm64<false><<<gproj, 256>>>(x, W2,  Q2W, BS, DM, SD, 0, 0, 0);

    // S = Q2W (3200x256) @ RT (256x800)
    sgemm64<false><<<dim3((NDELTA + 63) / 64, (BS + 63) / 64, 1), 256>>>(
        Q2W, RT, S, BS, NDELTA, DM, 0, 0, 0);

    // E[b] = Q[b] (400x256) @ K[b]^T (400x256)^T, batched over z
    sgemm64<true><<<dim3((SEQ + 63) / 64, (SEQ + 63) / 64, BATCH), 256>>>(
        Q, Kb, E, SEQ, SEQ, DM,
        (long)SEQ * DM, (long)SEQ * DM, (long)SEQ * SEQ);

    // Final combine + mask
    combine<<<(BSS + 255) / 256, 256>>>(E, S, mask, out, out_size);
}